// round 2
// baseline (speedup 1.0000x reference)
#include <cuda_runtime.h>
#include <cstdint>

// ---------------- problem constants ----------------
#define NROWS   16384      // 64*256*256 / 256
#define DDIM    256
#define KCODES  8192
#define DECAY   0.99f
#define ONE_M_DECAY 0.01f
#define EPSV    1e-5f

// output layout (concatenated, float32, tuple order)
#define OFF_Q     0L
#define OFF_LOSS  4194304L
#define OFF_IDX   4194305L
#define OFF_CS    4210689L
#define OFF_EMAW  4218881L
#define OFF_EMB   6316033L

// ---------------- scratch (device globals; no allocs allowed) ----------------
__device__ float g_emb [KCODES * DDIM];   // affine codebook, row-major [K][D]
__device__ float g_embT[DDIM * KCODES];   // transposed [D][K] for GEMM loads
__device__ float g_embsq[KCODES];
__device__ int   g_idx [NROWS];
__device__ float g_counts[KCODES];
__device__ float g_dw  [KCODES * DDIM];
__device__ float g_loss;
__device__ float g_nsum;

// ---------------- kernel 0: zero scratch ----------------
__global__ void zero_kernel() {
    long total = (long)KCODES * DDIM + KCODES + 2;
    for (long i = (long)blockIdx.x * blockDim.x + threadIdx.x; i < total;
         i += (long)gridDim.x * blockDim.x) {
        if (i < (long)KCODES * DDIM)            g_dw[i] = 0.f;
        else if (i < (long)KCODES * DDIM + KCODES) g_counts[i - (long)KCODES * DDIM] = 0.f;
        else if (i == (long)KCODES * DDIM + KCODES)     g_loss = 0.f;
        else                                            g_nsum = 0.f;
    }
}

// ---------------- kernel 1: affine transform + transpose + norms ----------------
// grid = KCODES blocks, 256 threads (one per d)
__global__ void prep_kernel(const float* __restrict__ embedding,
                            const float* __restrict__ amean,
                            const float* __restrict__ astd) {
    int k = blockIdx.x;
    int d = threadIdx.x;
    float v = amean[d] + astd[d] * embedding[(long)k * DDIM + d];
    g_emb[(long)k * DDIM + d] = v;
    g_embT[(long)d * KCODES + k] = v;

    // reduce v*v over block
    float s = v * v;
    #pragma unroll
    for (int off = 16; off; off >>= 1)
        s += __shfl_down_sync(0xffffffffu, s, off);
    __shared__ float ws[8];
    if ((d & 31) == 0) ws[d >> 5] = s;
    __syncthreads();
    if (d == 0) {
        float t = 0.f;
        #pragma unroll
        for (int i = 0; i < 8; i++) t += ws[i];
        g_embsq[k] = t;
    }
}

// ---------------- kernel 2: fused distance GEMM + argmin ----------------
// BM=64 rows per block, BN=256 codeword chunk, BK=8, 256 threads, 8x8 microtile.
#define BM 64
#define BN 256
#define BK 8
#define TM 8
#define TN 8
#define XS_STRIDE 68   // BM + 4 pad, multiple of 4 for float4 alignment

__global__ void __launch_bounds__(256, 2)
argmin_kernel(const float* __restrict__ x) {
    extern __shared__ float smem[];
    float* x_s = smem;                      // [DDIM][XS_STRIDE]
    float* e_s = smem + DDIM * XS_STRIDE;   // [BK][BN]

    const int tid = threadIdx.x;
    const int ty  = tid >> 5;    // 0..7  -> row group (warp id)
    const int tx  = tid & 31;    // 0..31 -> col group (lane)
    const int rowBase = blockIdx.x * BM;
    const int trow = ty * TM;
    const int tcol = tx * TN;

    // load x tile transposed: x_s[d][r] = x[rowBase+r][d]
    for (int i = tid; i < BM * DDIM; i += 256) {
        int r = i >> 8;        // i / 256
        int d = i & 255;
        x_s[d * XS_STRIDE + r] = x[(long)(rowBase + r) * DDIM + d];
    }

    float minv[TM];
    int   mini[TM];
    #pragma unroll
    for (int i = 0; i < TM; i++) { minv[i] = 3.4e38f; mini[i] = 0; }

    const int er = tid >> 5;          // 0..7  (BK row for staging)
    const int ec = (tid & 31) * 8;    // col base for staging

    for (int chunk = 0; chunk < KCODES / BN; chunk++) {
        float acc[TM][TN];
        #pragma unroll
        for (int i = 0; i < TM; i++)
            #pragma unroll
            for (int j = 0; j < TN; j++) acc[i][j] = 0.f;

        for (int kk = 0; kk < DDIM; kk += BK) {
            __syncthreads();
            // stage e_s[BK][BN] from g_embT (coalesced)
            {
                const float4* src = reinterpret_cast<const float4*>(
                    &g_embT[(long)(kk + er) * KCODES + chunk * BN + ec]);
                float4 v0 = src[0];
                float4 v1 = src[1];
                float4* dst = reinterpret_cast<float4*>(&e_s[er * BN + ec]);
                dst[0] = v0;
                dst[1] = v1;
            }
            __syncthreads();

            #pragma unroll
            for (int k = 0; k < BK; k++) {
                float a[TM], b[TN];
                const float4* ap = reinterpret_cast<const float4*>(
                    &x_s[(kk + k) * XS_STRIDE + trow]);
                float4 a0 = ap[0], a1 = ap[1];
                a[0]=a0.x; a[1]=a0.y; a[2]=a0.z; a[3]=a0.w;
                a[4]=a1.x; a[5]=a1.y; a[6]=a1.z; a[7]=a1.w;
                const float4* bp = reinterpret_cast<const float4*>(
                    &e_s[k * BN + tcol]);
                float4 b0 = bp[0], b1 = bp[1];
                b[0]=b0.x; b[1]=b0.y; b[2]=b0.z; b[3]=b0.w;
                b[4]=b1.x; b[5]=b1.y; b[6]=b1.z; b[7]=b1.w;
                #pragma unroll
                for (int i = 0; i < TM; i++)
                    #pragma unroll
                    for (int j = 0; j < TN; j++)
                        acc[i][j] += a[i] * b[j];
            }
        }

        // epilogue: score = ||e||^2 - 2 x.e ; keep running min (first index wins)
        #pragma unroll
        for (int j = 0; j < TN; j++) {
            int col = chunk * BN + tcol + j;
            float sq = g_embsq[col];
            #pragma unroll
            for (int i = 0; i < TM; i++) {
                float s = sq - 2.f * acc[i][j];
                if (s < minv[i]) { minv[i] = s; mini[i] = col; }
            }
        }
    }

    // warp reduction across 32 lanes (columns) per row; ties -> smaller index
    #pragma unroll
    for (int i = 0; i < TM; i++) {
        float v = minv[i];
        int   idx = mini[i];
        #pragma unroll
        for (int off = 16; off; off >>= 1) {
            float ov = __shfl_down_sync(0xffffffffu, v, off);
            int   oi = __shfl_down_sync(0xffffffffu, idx, off);
            if (ov < v || (ov == v && oi < idx)) { v = ov; idx = oi; }
        }
        if (tx == 0) g_idx[rowBase + trow + i] = idx;
    }
}

// ---------------- kernel 3: gather quantized, loss, scatter EMA stats ----------------
// grid = NROWS blocks, 256 threads (one per d)
__global__ void gather_kernel(const float* __restrict__ x, float* __restrict__ out) {
    int row = blockIdx.x;
    int d = threadIdx.x;
    int idx = g_idx[row];
    float xv = x[(long)row * DDIM + d];
    float qv = g_emb[(long)idx * DDIM + d];
    out[OFF_Q + (long)row * DDIM + d] = qv;

    float diff = qv - xv;
    float s = diff * diff;
    #pragma unroll
    for (int off = 16; off; off >>= 1)
        s += __shfl_down_sync(0xffffffffu, s, off);
    __shared__ float ws[8];
    if ((d & 31) == 0) ws[d >> 5] = s;
    __syncthreads();
    if (d == 0) {
        float t = 0.f;
        #pragma unroll
        for (int i = 0; i < 8; i++) t += ws[i];
        atomicAdd(&g_loss, t);
        atomicAdd(&g_counts[idx], 1.0f);
        out[OFF_IDX + row] = (float)idx;
    }
    atomicAdd(&g_dw[(long)idx * DDIM + d], xv);
}

// ---------------- kernel 4a: new_cluster_size + sum n ----------------
// grid = 32 blocks, 256 threads
__global__ void cs_kernel(const float* __restrict__ cluster_size, float* __restrict__ out) {
    int k = blockIdx.x * 256 + threadIdx.x;
    float ncs = cluster_size[k] * DECAY + ONE_M_DECAY * g_counts[k];
    out[OFF_CS + k] = ncs;
    float s = ncs;
    #pragma unroll
    for (int off = 16; off; off >>= 1)
        s += __shfl_down_sync(0xffffffffu, s, off);
    __shared__ float ws[8];
    if ((threadIdx.x & 31) == 0) ws[threadIdx.x >> 5] = s;
    __syncthreads();
    if (threadIdx.x == 0) {
        float t = 0.f;
        #pragma unroll
        for (int i = 0; i < 8; i++) t += ws[i];
        atomicAdd(&g_nsum, t);
    }
}

// ---------------- kernel 4b: new_ema_w ----------------
__global__ void emaw_kernel(const float* __restrict__ ema_w, float* __restrict__ out) {
    long i = (long)blockIdx.x * blockDim.x + threadIdx.x;
    if (i < (long)KCODES * DDIM)
        out[OFF_EMAW + i] = ema_w[i] * DECAY + ONE_M_DECAY * g_dw[i];
}

// ---------------- kernel 5: smoothed normalize + loss write ----------------
// grid = KCODES blocks, 256 threads
__global__ void final_kernel(float* __restrict__ out) {
    int k = blockIdx.x;
    int d = threadIdx.x;
    float n = g_nsum;
    float ncs = out[OFF_CS + k];
    float smoothed = (ncs + EPSV) / (n + (float)KCODES * EPSV) * n;
    out[OFF_EMB + (long)k * DDIM + d] = out[OFF_EMAW + (long)k * DDIM + d] / smoothed;
    if (k == 0 && d == 0)
        out[OFF_LOSS] = 2.0f * g_loss / (float)((long)NROWS * DDIM);
}

// ---------------- launch ----------------
extern "C" void kernel_launch(void* const* d_in, const int* in_sizes, int n_in,
                              void* d_out, int out_size) {
    const float* x         = (const float*)d_in[0];
    const float* embedding = (const float*)d_in[1];
    const float* amean     = (const float*)d_in[2];
    const float* astd      = (const float*)d_in[3];
    const float* cs        = (const float*)d_in[4];
    const float* ema_w     = (const float*)d_in[5];
    float* out = (float*)d_out;

    (void)in_sizes; (void)n_in; (void)out_size;

    size_t smem = (DDIM * XS_STRIDE + BK * BN) * sizeof(float);  // ~78 KB
    cudaFuncSetAttribute(argmin_kernel, cudaFuncAttributeMaxDynamicSharedMemorySize,
                         (int)smem);

    zero_kernel<<<2048, 256>>>();
    prep_kernel<<<KCODES, 256>>>(embedding, amean, astd);
    argmin_kernel<<<NROWS / BM, 256, smem>>>(x);
    gather_kernel<<<NROWS, 256>>>(x, out);
    cs_kernel<<<KCODES / 256, 256>>>(cs, out);
    emaw_kernel<<<(KCODES * DDIM + 255) / 256, 256>>>(ema_w, out);
    final_kernel<<<KCODES, 256>>>(out);
}